// round 6
// baseline (speedup 1.0000x reference)
#include <cuda_runtime.h>

#define NL  2048
#define NE  256
#define NH  8
#define NHW 32
#define NB  2
#define KS  4              // k-split factor
#define KT  16             // key tile

// Scratch (static device globals -- no runtime allocation)
__device__ float g_Q [NB*NH*NL*NHW];      // [bh][l][d] (pre-scaled)
__device__ float g_Kt[NB*NH*NHW*NL];      // [bh][d][l]
__device__ float g_V [NB*NH*NL*NHW];      // [bh][l][d]
__device__ float g_Y [NB*NL*NE];
__device__ float g_Opart[KS*NB*NL*NE];    // partial numerators
__device__ float g_Lpart[KS*NB*NL*NH];    // partial denominators

typedef unsigned long long u64;

static __device__ __forceinline__ u64 pack2(float lo, float hi) {
    u64 r; asm("mov.b64 %0, {%1,%2};" : "=l"(r) : "f"(lo), "f"(hi)); return r;
}
static __device__ __forceinline__ void unpack2(u64 a, float& lo, float& hi) {
    asm("mov.b64 {%0,%1}, %2;" : "=f"(lo), "=f"(hi) : "l"(a));
}
static __device__ __forceinline__ void fma2(u64& acc, u64 a, u64 b) {
    asm("fma.rn.f32x2 %0, %1, %2, %3;" : "=l"(acc) : "l"(a), "l"(b), "l"(acc));
}
static __device__ __forceinline__ void cp16(void* dst, const void* src) {
    unsigned d = (unsigned)__cvta_generic_to_shared(dst);
    asm volatile("cp.async.cg.shared.global [%0], [%1], 16;" :: "r"(d), "l"(src));
}
static __device__ __forceinline__ void cp_commit() {
    asm volatile("cp.async.commit_group;");
}
static __device__ __forceinline__ void cp_wait1() {
    asm volatile("cp.async.wait_group 1;");
}

// ---------------------------------------------------------------------------
// GEMM (NT): C[m][n] = sum_k A[m][k]*W[n][k], K=256. 128x64 tile, 256 thr,
// 8m x 4n micro-tile (m-paired f32x2). EPI 0: scatter Q/Kt/V. EPI 1: +bias.
// ---------------------------------------------------------------------------
template<int EPI>
__global__ __launch_bounds__(256) void gemm_nt(const float* __restrict__ A,
                                               const float* __restrict__ W,
                                               const float* __restrict__ bo,
                                               float* __restrict__ out)
{
    __shared__ __align__(16) float As[32][132];
    __shared__ __align__(16) float Bs[32][68];
    const int tid = threadIdx.x;
    const int tx = tid & 15, ty = tid >> 4;
    const int m0 = blockIdx.x * 128, n0 = blockIdx.y * 64;

    u64 acc[4][4];
    #pragma unroll
    for (int p = 0; p < 4; p++)
        #pragma unroll
        for (int j = 0; j < 4; j++) acc[p][j] = 0ULL;

    for (int kc = 0; kc < 256; kc += 32) {
        #pragma unroll
        for (int r = 0; r < 4; r++) {
            int idx = tid + r * 256;
            int row = idx >> 3, c4 = (idx & 7) << 2;
            float4 xa = *(const float4*)&A[(size_t)(m0 + row) * 256 + kc + c4];
            As[c4+0][row] = xa.x; As[c4+1][row] = xa.y;
            As[c4+2][row] = xa.z; As[c4+3][row] = xa.w;
        }
        #pragma unroll
        for (int r = 0; r < 2; r++) {
            int idx = tid + r * 256;
            int row = idx >> 3, c4 = (idx & 7) << 2;
            float4 wa = *(const float4*)&W[(size_t)(n0 + row) * 256 + kc + c4];
            Bs[c4+0][row] = wa.x; Bs[c4+1][row] = wa.y;
            Bs[c4+2][row] = wa.z; Bs[c4+3][row] = wa.w;
        }
        __syncthreads();
        #pragma unroll
        for (int k = 0; k < 32; k++) {
            ulonglong2 aA = *(const ulonglong2*)&As[k][ty * 8];
            ulonglong2 aB = *(const ulonglong2*)&As[k][ty * 8 + 4];
            float4 b4 = *(const float4*)&Bs[k][tx * 4];
            u64 bb;
            bb = pack2(b4.x, b4.x);
            fma2(acc[0][0], aA.x, bb); fma2(acc[1][0], aA.y, bb);
            fma2(acc[2][0], aB.x, bb); fma2(acc[3][0], aB.y, bb);
            bb = pack2(b4.y, b4.y);
            fma2(acc[0][1], aA.x, bb); fma2(acc[1][1], aA.y, bb);
            fma2(acc[2][1], aB.x, bb); fma2(acc[3][1], aB.y, bb);
            bb = pack2(b4.z, b4.z);
            fma2(acc[0][2], aA.x, bb); fma2(acc[1][2], aA.y, bb);
            fma2(acc[2][2], aB.x, bb); fma2(acc[3][2], aB.y, bb);
            bb = pack2(b4.w, b4.w);
            fma2(acc[0][3], aA.x, bb); fma2(acc[1][3], aA.y, bb);
            fma2(acc[2][3], aB.x, bb); fma2(acc[3][3], aB.y, bb);
        }
        __syncthreads();
    }

    #pragma unroll
    for (int p = 0; p < 4; p++) {
        int m = m0 + ty * 8 + 2 * p;
        #pragma unroll
        for (int j = 0; j < 4; j++) {
            float v0, v1; unpack2(acc[p][j], v0, v1);
            int n = n0 + tx * 4 + j;
            if (EPI == 0) {
                int hh = n / 96, rem = n % 96;
                int part = rem >> 5, c = rem & 31;
                int bb_ = m >> 11, l = m & 2047;
                int bh = bb_ * NH + hh;
                if (part == 1) {
                    float* d = g_Kt + (size_t)bh * (NHW * NL) + (size_t)c * NL + l;
                    d[0] = v0; d[1] = v1;
                } else {
                    float* d = (part == 0 ? g_Q : g_V)
                             + ((size_t)bh * NL + l) * NHW + c;
                    float sc = (part == 0) ? 0.17677669529663687f : 1.0f;
                    d[0]   = v0 * sc;
                    d[NHW] = v1 * sc;
                }
            } else {
                float bias_ = bo[n];
                out[(size_t)m * NE + n]       = v0 + bias_;
                out[(size_t)(m + 1) * NE + n] = v1 + bias_;
            }
        }
    }
}

// ---------------------------------------------------------------------------
// Attention v3c: lane=query, warp=head, CTA = 32q x 8h over a 512-key split.
// k-tile 16, smem 96KB -> 2 CTAs/SM (4 warps/SMSP). Bias smem XOR-swizzled.
// Writes partial (numerator, denominator) -- combined exactly by reduce_k.
// ---------------------------------------------------------------------------
// smem float offsets
#define SM_K   0            // [h][s][d32][k16]    8*2*32*16
#define SM_V2  8192         // [h][s][k16][d32]    8*2*16*32
#define SM_B   16384        // [s][q32][32 units of 4w, XOR-swizzled] 2*4096
#define SMEMF  24576
#define SMEMB  (SMEMF*4)

__global__ __launch_bounds__(256, 2) void attn3(const float* __restrict__ bias)
{
    extern __shared__ float sm[];
    const int tid = threadIdx.x, lane = tid & 31, h = tid >> 5;
    const int q0 = blockIdx.x * 32;
    const int b  = blockIdx.y >> 2;
    const int ks = blockIdx.y & 3;
    const int bh = b * NH + h;
    const int kbase0 = ks * (NL / KS);

    const float* Ktb = g_Kt + (size_t)bh * (NHW * NL);
    const float* Vb  = g_V  + (size_t)bh * (NL * NHW);

    float qreg[32];
    {
        const float4* qp = (const float4*)(g_Q + ((size_t)bh * NL + q0 + lane) * NHW);
        #pragma unroll
        for (int i = 0; i < 8; i++) *(float4*)&qreg[i * 4] = qp[i];
    }

    u64 o2[16];
    #pragma unroll
    for (int i = 0; i < 16; i++) o2[i] = 0ULL;
    float lsum0 = 0.f, lsum1 = 0.f;

    float* kW = sm + SM_K  + h * 1024;
    float* vW = sm + SM_V2 + h * 1024;
    const size_t brow = ((size_t)(b * NL + q0)) * (NL * NH);

    auto stage = [&](int s, int kb) {
        // K^T tile for this head: 32d x 16k
        #pragma unroll
        for (int i = 0; i < 4; i++) {
            int m = i * 32 + lane, d = m >> 2, j = m & 3;
            cp16(kW + s * 512 + d * 16 + j * 4,
                 Ktb + (size_t)d * NL + kb + j * 4);
        }
        // V tile: 16k x 32d (contiguous)
        #pragma unroll
        for (int i = 0; i < 4; i++) {
            int m = i * 32 + lane, k = m >> 3, j = m & 7;
            cp16(vW + s * 512 + k * 32 + j * 4,
                 Vb + (size_t)(kb + k) * NHW + j * 4);
        }
        // bias tile: 32q x 16k x 8h, unit u = k*2 + hgrp, swizzled u^(q&31)
        #pragma unroll
        for (int i = 0; i < 4; i++) {
            int m = i * 256 + tid, q = m >> 5, u = m & 31;
            cp16(sm + SM_B + s * 4096 + q * 128 + ((u ^ (q & 31)) << 2),
                 bias + brow + (size_t)q * (NL * NH)
                      + (size_t)(kb + (u >> 1)) * NH + (u & 1) * 4);
        }
    };

    stage(0, kbase0);
    cp_commit();

    const int qm = lane & 31;
    const int hg = h >> 2, h3 = h & 3;

    for (int t = 0; t < (NL / KS) / KT; t++) {
        int s = t & 1;
        if (t < (NL / KS) / KT - 1) stage(s ^ 1, kbase0 + (t + 1) * KT);
        cp_commit();
        cp_wait1();
        __syncthreads();

        // phase 1: scores for ALL 16 keys (4 x ulonglong2 per d-row)
        u64 s2[8];
        #pragma unroll
        for (int i = 0; i < 8; i++) s2[i] = 0ULL;
        const float* kp = kW + s * 512;
        #pragma unroll
        for (int d = 0; d < 32; d++) {
            u64 qq = pack2(qreg[d], qreg[d]);
            const ulonglong2* kr = (const ulonglong2*)(kp + d * 16);
            #pragma unroll
            for (int i = 0; i < 4; i++) {
                ulonglong2 kk = kr[i];
                fma2(s2[2 * i],     kk.x, qq);
                fma2(s2[2 * i + 1], kk.y, qq);
            }
        }

        // exp(score + bias); no max subtraction (bounded scores, fp32 safe)
        float p[16];
        const float* bbase = sm + SM_B + s * 4096 + lane * 128;
        #pragma unroll
        for (int j = 0; j < 8; j++) {
            float sa, sb; unpack2(s2[j], sa, sb);
            int k0i = 2 * j, k1i = 2 * j + 1;
            float b0 = bbase[(((k0i * 2 + hg) ^ qm) << 2) + h3];
            float b1 = bbase[(((k1i * 2 + hg) ^ qm) << 2) + h3];
            float p0 = __expf(sa + b0);
            float p1 = __expf(sb + b1);
            p[k0i] = p0; p[k1i] = p1;
            lsum0 += p0; lsum1 += p1;
        }

        // phase 2: o[d] += p[k] * V[k][d]   (full d range: 8 x ulonglong2)
        const float* vp = vW + s * 512;
        #pragma unroll
        for (int k = 0; k < 16; k++) {
            u64 pp = pack2(p[k], p[k]);
            const ulonglong2* vr = (const ulonglong2*)(vp + k * 32);
            #pragma unroll
            for (int i = 0; i < 8; i++) {
                ulonglong2 vv2 = vr[i];
                fma2(o2[2 * i],     vv2.x, pp);
                fma2(o2[2 * i + 1], vv2.y, pp);
            }
        }
        __syncthreads();
    }

    // write partials
    float* op = g_Opart + (((size_t)(ks * NB + b) * NL + q0 + lane)) * NE + h * NHW;
    #pragma unroll
    for (int i = 0; i < 8; i++) {
        float a0, a1, a2, a3;
        unpack2(o2[2 * i],     a0, a1);
        unpack2(o2[2 * i + 1], a2, a3);
        ((float4*)op)[i] = make_float4(a0, a1, a2, a3);
    }
    g_Lpart[((size_t)(ks * NB + b) * NL + q0 + lane) * NH + h] = lsum0 + lsum1;
}

// ---------------------------------------------------------------------------
// combine k-split partials: y = (sum_s o_s) / (sum_s l_s)
// ---------------------------------------------------------------------------
__global__ __launch_bounds__(256) void reduce_k()
{
    int idx = blockIdx.x * 256 + threadIdx.x;       // over NB*NL*NE
    int e = idx & 255;
    int bl = idx >> 8;                               // b*NL + l
    int hh = e >> 5;
    float o = 0.f, l = 0.f;
    #pragma unroll
    for (int s = 0; s < KS; s++) {
        o += g_Opart[((size_t)s * NB * NL + bl) * NE + e];
        l += g_Lpart[((size_t)s * NB * NL + bl) * NH + hh];
    }
    g_Y[(size_t)bl * NE + e] = o / l;
}

// ---------------------------------------------------------------------------
extern "C" void kernel_launch(void* const* d_in, const int* in_sizes, int n_in,
                              void* d_out, int out_size)
{
    const float* x    = (const float*)d_in[0];
    const float* bias = (const float*)d_in[1];
    const float* Wp   = (const float*)d_in[2];
    const float* Wo   = (const float*)d_in[3];
    const float* bo   = (const float*)d_in[4];
    float* out = (float*)d_out;

    float* yptr;
    cudaGetSymbolAddress((void**)&yptr, g_Y);

    cudaFuncSetAttribute(attn3, cudaFuncAttributeMaxDynamicSharedMemorySize,
                         SMEMB);

    gemm_nt<0><<<dim3(32, 12), 256>>>(x, Wp, nullptr, nullptr);
    attn3<<<dim3(NL / 32, NB * KS), 256, SMEMB>>>(bias);
    reduce_k<<<(NB * NL * NE) / 256, 256>>>();
    gemm_nt<1><<<dim3(32, 4), 256>>>(yptr, Wo, bo, out);
}